// round 2
// baseline (speedup 1.0000x reference)
#include <cuda_runtime.h>
#include <math.h>

#define T_TOK 524288
#define D_DIM 256
#define N_SEG 8192

// Scratch (allocation-free rule: __device__ globals). 16B-aligned for float4.
__device__ __align__(16) float g_mean[N_SEG * D_DIM];   // per-segment mean
__device__ __align__(16) float g_tg[N_SEG * D_DIM];     // tanh(mean @ W)

__device__ __forceinline__ int lower_bound_dev(const int* __restrict__ a, int n, int key) {
    int lo = 0, hi = n;
    while (lo < hi) {
        int mid = (lo + hi) >> 1;
        if (__ldg(a + mid) < key) lo = mid + 1; else hi = mid;
    }
    return lo;
}

// ---------------------------------------------------------------------------
// Pass 1: per-segment column sums -> mean.  One block (256 thr) per segment,
// thread tid owns column tid. Contiguous token range => coalesced, no atomics.
// ---------------------------------------------------------------------------
__global__ void k_segmean(const float* __restrict__ emb, const int* __restrict__ obj) {
    int n = blockIdx.x, tid = threadIdx.x;
    __shared__ int sb[2];
    if (tid == 0)       sb[0] = lower_bound_dev(obj, T_TOK, n);
    else if (tid == 32) sb[1] = lower_bound_dev(obj, T_TOK, n + 1);
    __syncthreads();
    int s = sb[0], e = sb[1];

    float a0 = 0.f, a1 = 0.f, a2 = 0.f, a3 = 0.f;
    int t = s;
    for (; t + 4 <= e; t += 4) {
        a0 += emb[(size_t)(t + 0) * D_DIM + tid];
        a1 += emb[(size_t)(t + 1) * D_DIM + tid];
        a2 += emb[(size_t)(t + 2) * D_DIM + tid];
        a3 += emb[(size_t)(t + 3) * D_DIM + tid];
    }
    for (; t < e; ++t) a0 += emb[(size_t)t * D_DIM + tid];
    float acc = (a0 + a1) + (a2 + a3);
    float cnt = (float)(e - s);
    g_mean[(size_t)n * D_DIM + tid] = acc / fmaxf(cnt, 1.f);
}

// ---------------------------------------------------------------------------
// Pass 2: g_tg = tanh(g_mean @ W).  [8192,256] x [256,256], tiled SGEMM:
// BM=BN=64, BK=16, 256 threads, 4x4 register tile.
// ---------------------------------------------------------------------------
__global__ void k_gemm_tanh(const float* __restrict__ W) {
    __shared__ __align__(16) float As[16][64];
    __shared__ __align__(16) float Bs[16][64];
    int tid = threadIdx.x;
    int tx = tid & 15, ty = tid >> 4;
    int bm = blockIdx.x * 64, bn = blockIdx.y * 64;

    int ar  = tid >> 2;          // 0..63 (A tile row)
    int ak4 = (tid & 3) * 4;     // 0,4,8,12 (A tile k start)
    int br  = tid >> 4;          // 0..15 (B tile row = k)
    int bc4 = (tid & 15) * 4;    // 0..60 (B tile col start)

    float acc[4][4] = {};
    for (int k0 = 0; k0 < 256; k0 += 16) {
        float4 av = *(const float4*)(g_mean + (size_t)(bm + ar) * 256 + k0 + ak4);
        float4 bv = *(const float4*)(W + (size_t)(k0 + br) * 256 + bn + bc4);
        As[ak4 + 0][ar] = av.x;
        As[ak4 + 1][ar] = av.y;
        As[ak4 + 2][ar] = av.z;
        As[ak4 + 3][ar] = av.w;
        *(float4*)&Bs[br][bc4] = bv;
        __syncthreads();
#pragma unroll
        for (int k = 0; k < 16; ++k) {
            float a[4], b[4];
            *(float4*)a = *(const float4*)&As[k][ty * 4];
            *(float4*)b = *(const float4*)&Bs[k][tx * 4];
#pragma unroll
            for (int i = 0; i < 4; ++i)
#pragma unroll
                for (int j = 0; j < 4; ++j)
                    acc[i][j] += a[i] * b[j];
        }
        __syncthreads();
    }
#pragma unroll
    for (int i = 0; i < 4; ++i) {
        float4 o;
        o.x = tanhf(acc[i][0]);
        o.y = tanhf(acc[i][1]);
        o.z = tanhf(acc[i][2]);
        o.w = tanhf(acc[i][3]);
        *(float4*)(g_tg + (size_t)(bm + ty * 4 + i) * 256 + bn + tx * 4) = o;
    }
}

// ---------------------------------------------------------------------------
// Pass 3 (fused): per-token sigmoid score, per-segment weighted sum (rep),
// then broadcast rep back to every token of the segment (final output).
// One block per segment; warp-per-token dot products; shared-atomic combine;
// float4 broadcast stores.
// ---------------------------------------------------------------------------
__global__ void k_score_rep_bcast(const float* __restrict__ emb,
                                  const int* __restrict__ obj,
                                  float* __restrict__ out) {
    int n = blockIdx.x, tid = threadIdx.x;
    __shared__ int sb[2];
    __shared__ __align__(16) float stg[256];
    __shared__ __align__(16) float srep[256];
    if (tid == 0)       sb[0] = lower_bound_dev(obj, T_TOK, n);
    else if (tid == 32) sb[1] = lower_bound_dev(obj, T_TOK, n + 1);
    stg[tid]  = g_tg[(size_t)n * 256 + tid];
    srep[tid] = 0.f;
    __syncthreads();
    int s = sb[0], e = sb[1];
    int lane = tid & 31, w = tid >> 5;

    float4 tga = *(const float4*)&stg[lane * 8];
    float4 tgb = *(const float4*)&stg[lane * 8 + 4];
    float acc[8] = {0.f, 0.f, 0.f, 0.f, 0.f, 0.f, 0.f, 0.f};

    for (int t = s + w; t < e; t += 8) {
        const float4* ep = (const float4*)(emb + (size_t)t * 256 + lane * 8);
        float4 ea = ep[0], eb = ep[1];
        float d = ea.x * tga.x + ea.y * tga.y + ea.z * tga.z + ea.w * tga.w
                + eb.x * tgb.x + eb.y * tgb.y + eb.z * tgb.z + eb.w * tgb.w;
#pragma unroll
        for (int off = 16; off; off >>= 1)
            d += __shfl_xor_sync(0xffffffffu, d, off);
        float sc = 1.f / (1.f + expf(-d));
        acc[0] += ea.x * sc; acc[1] += ea.y * sc;
        acc[2] += ea.z * sc; acc[3] += ea.w * sc;
        acc[4] += eb.x * sc; acc[5] += eb.y * sc;
        acc[6] += eb.z * sc; acc[7] += eb.w * sc;
    }
#pragma unroll
    for (int i = 0; i < 8; ++i)
        atomicAdd(&srep[lane * 8 + i], acc[i]);
    __syncthreads();

    // Broadcast rep to all tokens of the segment: 4 tokens per pass, float4.
    int c = tid & 63;     // float4 column 0..63
    int r = tid >> 6;     // token sub-row 0..3
    float4 rv = *(const float4*)&srep[c * 4];
    for (int t = s + r; t < e; t += 4)
        ((float4*)out)[(size_t)t * 64 + c] = rv;
}

extern "C" void kernel_launch(void* const* d_in, const int* in_sizes, int n_in,
                              void* d_out, int out_size) {
    const float* emb = (const float*)d_in[0];
    const float* W   = (const float*)d_in[1];
    const int*   obj = (const int*)d_in[2];
    float*       out = (float*)d_out;

    k_segmean<<<N_SEG, 256>>>(emb, obj);
    k_gemm_tanh<<<dim3(N_SEG / 64, D_DIM / 64), 256>>>(W);
    k_score_rep_bcast<<<N_SEG, 256>>>(emb, obj, out);
}

// round 3
// speedup vs baseline: 1.1600x; 1.1600x over previous
#include <cuda_runtime.h>
#include <math.h>

#define T_TOK 524288
#define D_DIM 256
#define N_SEG 8192

__device__ __align__(16) float g_mean[N_SEG * D_DIM];
__device__ __align__(16) float g_tg[N_SEG * D_DIM];

__device__ __forceinline__ int lower_bound_dev(const int* __restrict__ a, int n, int key) {
    int lo = 0, hi = n;
    while (lo < hi) {
        int mid = (lo + hi) >> 1;
        if (__ldg(a + mid) < key) lo = mid + 1; else hi = mid;
    }
    return lo;
}

// ---------------------------------------------------------------------------
// Pass 1: per-segment mean. One block per segment. float4 loads, 4 token-rows
// per iteration: thread owns float4 column chunk (tid&63)*4 of row-group tid>>6.
// ---------------------------------------------------------------------------
__global__ void k_segmean(const float* __restrict__ emb, const int* __restrict__ obj) {
    int n = blockIdx.x, tid = threadIdx.x;
    __shared__ int sb[2];
    __shared__ __align__(16) float red[4][256];
    if (tid == 0)       sb[0] = lower_bound_dev(obj, T_TOK, n);
    else if (tid == 32) sb[1] = lower_bound_dev(obj, T_TOK, n + 1);
    __syncthreads();
    int s = sb[0], e = sb[1];

    int r = tid >> 6;           // row-group 0..3
    int c4 = (tid & 63) * 4;    // column start
    float4 acc = make_float4(0.f, 0.f, 0.f, 0.f);
#pragma unroll 4
    for (int t = s + r; t < e; t += 4) {
        float4 v = *(const float4*)(emb + (size_t)t * D_DIM + c4);
        acc.x += v.x; acc.y += v.y; acc.z += v.z; acc.w += v.w;
    }
    *(float4*)&red[r][c4] = acc;
    __syncthreads();

    float sum = red[0][tid] + red[1][tid] + red[2][tid] + red[3][tid];
    g_mean[(size_t)n * D_DIM + tid] = sum / fmaxf((float)(e - s), 1.f);
}

// ---------------------------------------------------------------------------
// Pass 2: g_tg = tanh(g_mean @ W). Tiled SGEMM, BM=BN=64, BK=16, 4x4 reg tile.
// ---------------------------------------------------------------------------
__global__ void k_gemm_tanh(const float* __restrict__ W) {
    __shared__ __align__(16) float As[16][64];
    __shared__ __align__(16) float Bs[16][64];
    int tid = threadIdx.x;
    int tx = tid & 15, ty = tid >> 4;
    int bm = blockIdx.x * 64, bn = blockIdx.y * 64;

    int ar  = tid >> 2;
    int ak4 = (tid & 3) * 4;
    int br  = tid >> 4;
    int bc4 = (tid & 15) * 4;

    float acc[4][4] = {};
    for (int k0 = 0; k0 < 256; k0 += 16) {
        float4 av = *(const float4*)(g_mean + (size_t)(bm + ar) * 256 + k0 + ak4);
        float4 bv = *(const float4*)(W + (size_t)(k0 + br) * 256 + bn + bc4);
        As[ak4 + 0][ar] = av.x;
        As[ak4 + 1][ar] = av.y;
        As[ak4 + 2][ar] = av.z;
        As[ak4 + 3][ar] = av.w;
        *(float4*)&Bs[br][bc4] = bv;
        __syncthreads();
#pragma unroll
        for (int k = 0; k < 16; ++k) {
            float a[4], b[4];
            *(float4*)a = *(const float4*)&As[k][ty * 4];
            *(float4*)b = *(const float4*)&Bs[k][tx * 4];
#pragma unroll
            for (int i = 0; i < 4; ++i)
#pragma unroll
                for (int j = 0; j < 4; ++j)
                    acc[i][j] += a[i] * b[j];
        }
        __syncthreads();
    }
#pragma unroll
    for (int i = 0; i < 4; ++i) {
        float4 o;
        o.x = tanhf(acc[i][0]);
        o.y = tanhf(acc[i][1]);
        o.z = tanhf(acc[i][2]);
        o.w = tanhf(acc[i][3]);
        *(float4*)(g_tg + (size_t)(bm + ty * 4 + i) * 256 + bn + tx * 4) = o;
    }
}

// ---------------------------------------------------------------------------
// Pass 3 (fused): scores + weighted segment sum + broadcast. One block per
// segment; each warp processes TWO tokens per iteration (independent dot/shfl
// chains interleaved to hide shuffle latency).
// ---------------------------------------------------------------------------
__global__ void k_score_rep_bcast(const float* __restrict__ emb,
                                  const int* __restrict__ obj,
                                  float* __restrict__ out) {
    int n = blockIdx.x, tid = threadIdx.x;
    __shared__ int sb[2];
    __shared__ __align__(16) float stg[256];
    __shared__ __align__(16) float srep[256];
    if (tid == 0)       sb[0] = lower_bound_dev(obj, T_TOK, n);
    else if (tid == 32) sb[1] = lower_bound_dev(obj, T_TOK, n + 1);
    stg[tid]  = g_tg[(size_t)n * 256 + tid];
    srep[tid] = 0.f;
    __syncthreads();
    int s = sb[0], e = sb[1];
    int lane = tid & 31, w = tid >> 5;

    float4 tga = *(const float4*)&stg[lane * 8];
    float4 tgb = *(const float4*)&stg[lane * 8 + 4];
    float acc[8] = {0.f, 0.f, 0.f, 0.f, 0.f, 0.f, 0.f, 0.f};

    int t = s + 2 * w;
    for (; t + 1 < e; t += 16) {
        const float4* e0 = (const float4*)(emb + (size_t)t * 256 + lane * 8);
        const float4* e1 = (const float4*)(emb + (size_t)(t + 1) * 256 + lane * 8);
        float4 a0 = e0[0], b0 = e0[1];
        float4 a1 = e1[0], b1 = e1[1];
        float d0 = a0.x * tga.x + a0.y * tga.y + a0.z * tga.z + a0.w * tga.w
                 + b0.x * tgb.x + b0.y * tgb.y + b0.z * tgb.z + b0.w * tgb.w;
        float d1 = a1.x * tga.x + a1.y * tga.y + a1.z * tga.z + a1.w * tga.w
                 + b1.x * tgb.x + b1.y * tgb.y + b1.z * tgb.z + b1.w * tgb.w;
#pragma unroll
        for (int off = 16; off; off >>= 1) {
            d0 += __shfl_xor_sync(0xffffffffu, d0, off);
            d1 += __shfl_xor_sync(0xffffffffu, d1, off);
        }
        float s0 = 1.f / (1.f + expf(-d0));
        float s1 = 1.f / (1.f + expf(-d1));
        acc[0] += a0.x * s0 + a1.x * s1;
        acc[1] += a0.y * s0 + a1.y * s1;
        acc[2] += a0.z * s0 + a1.z * s1;
        acc[3] += a0.w * s0 + a1.w * s1;
        acc[4] += b0.x * s0 + b1.x * s1;
        acc[5] += b0.y * s0 + b1.y * s1;
        acc[6] += b0.z * s0 + b1.z * s1;
        acc[7] += b0.w * s0 + b1.w * s1;
    }
    if (t < e) {
        const float4* e0 = (const float4*)(emb + (size_t)t * 256 + lane * 8);
        float4 a0 = e0[0], b0 = e0[1];
        float d0 = a0.x * tga.x + a0.y * tga.y + a0.z * tga.z + a0.w * tga.w
                 + b0.x * tgb.x + b0.y * tgb.y + b0.z * tgb.z + b0.w * tgb.w;
#pragma unroll
        for (int off = 16; off; off >>= 1)
            d0 += __shfl_xor_sync(0xffffffffu, d0, off);
        float s0 = 1.f / (1.f + expf(-d0));
        acc[0] += a0.x * s0; acc[1] += a0.y * s0;
        acc[2] += a0.z * s0; acc[3] += a0.w * s0;
        acc[4] += b0.x * s0; acc[5] += b0.y * s0;
        acc[6] += b0.z * s0; acc[7] += b0.w * s0;
    }
#pragma unroll
    for (int i = 0; i < 8; ++i)
        atomicAdd(&srep[lane * 8 + i], acc[i]);
    __syncthreads();

    int c = tid & 63;
    int r = tid >> 6;
    float4 rv = *(const float4*)&srep[c * 4];
    for (int tt = s + r; tt < e; tt += 4)
        ((float4*)out)[(size_t)tt * 64 + c] = rv;
}

extern "C" void kernel_launch(void* const* d_in, const int* in_sizes, int n_in,
                              void* d_out, int out_size) {
    const float* emb = (const float*)d_in[0];
    const float* W   = (const float*)d_in[1];
    const int*   obj = (const int*)d_in[2];
    float*       out = (float*)d_out;

    k_segmean<<<N_SEG, 256>>>(emb, obj);
    k_gemm_tanh<<<dim3(N_SEG / 64, D_DIM / 64), 256>>>(W);
    k_score_rep_bcast<<<N_SEG, 256>>>(emb, obj, out);
}